// round 13
// baseline (speedup 1.0000x reference)
#include <cuda_runtime.h>
#include <cuda_bf16.h>
#include <cstdint>
#include <math.h>

#define B_ROWS 32768
#define N_CODE 8192
#define DIM    512
#define BD     (B_ROWS * DIM)

#define UNITS  16384           // 256 mt x 64 nt, unit tile 128x128
#define NKC    8               // K-chunks of 64 (K=512, hi-only)
#define STAGES 3
#define STAGE_BYTES 32768      // A 16K (128x128B) + B 16K (128x128B)
#define SMEM_TOTAL (STAGES * STAGE_BYTES)   // 96 KB -> 2 CTAs/SM

#define CAP    128
#define MARGIN 0.75f

// ---------------- device scratch ----------------
__device__ __nv_bfloat16 g_Az[(size_t)B_ROWS * DIM];   // 32 MB (hi only)
__device__ __nv_bfloat16 g_Bw[(size_t)N_CODE * DIM];   // 8 MB
__device__ float g_zz[B_ROWS];
__device__ float g_wn[N_CODE];
__device__ unsigned g_rmin[B_ROWS];        // ordered-float running min
__device__ int g_ccnt[B_ROWS];
__device__ int g_cand[(size_t)B_ROWS * CAP];   // 16 MB
__device__ int g_counts[N_CODE];
__device__ float g_rowsse[B_ROWS];

// ---------------- helpers ----------------
__device__ __forceinline__ uint32_t smem_u32(const void* p) {
    uint32_t a;
    asm("{ .reg .u64 t; cvta.to.shared.u64 t, %1; cvt.u32.u64 %0, t; }" : "=r"(a) : "l"(p));
    return a;
}
__device__ __forceinline__ void cp16(uint32_t dst, const void* src) {
    asm volatile("cp.async.cg.shared.global [%0], [%1], 16;" :: "r"(dst), "l"(src));
}
#define CP_COMMIT() asm volatile("cp.async.commit_group;" ::: "memory")
#define CP_WAIT0()  asm volatile("cp.async.wait_group 0;" ::: "memory")
#define CP_WAIT1()  asm volatile("cp.async.wait_group 1;" ::: "memory")

#define LDM_X4(r0, r1, r2, r3, a)                                              \
    asm volatile("ldmatrix.sync.aligned.m8n8.x4.shared.b16 {%0,%1,%2,%3}, [%4];" \
        : "=r"(r0), "=r"(r1), "=r"(r2), "=r"(r3) : "r"(a))

#define MMA_BF16(d, a, b)                                                      \
    asm volatile("mma.sync.aligned.m16n8k16.row.col.f32.bf16.bf16.f32 "        \
        "{%0,%1,%2,%3},{%4,%5,%6,%7},{%8,%9},{%0,%1,%2,%3};"                   \
        : "+f"((d)[0]), "+f"((d)[1]), "+f"((d)[2]), "+f"((d)[3])               \
        : "r"((a)[0]), "r"((a)[1]), "r"((a)[2]), "r"((a)[3]),                  \
          "r"((b)[0]), "r"((b)[1]))

__device__ __forceinline__ uint32_t f2ord(float f) {
    uint32_t u = __float_as_uint(f);
    return (u & 0x80000000u) ? ~u : (u | 0x80000000u);
}
__device__ __forceinline__ float ord2f(uint32_t k) {
    return (k & 0x80000000u) ? __uint_as_float(k ^ 0x80000000u)
                             : __uint_as_float(~k);
}

// ---------------- fused pack (fp32 -> bf16 hi) + row norm ----------------
__global__ void packnorm_z_kernel(const float* __restrict__ x) {
    int warp = (blockIdx.x * blockDim.x + threadIdx.x) >> 5;
    int lane = threadIdx.x & 31;
    if (warp >= B_ROWS) return;
    const float4* p = (const float4*)(x + (size_t)warp * DIM);
    __nv_bfloat162* dst = (__nv_bfloat162*)(g_Az + (size_t)warp * DIM);
    float s = 0.0f;
    #pragma unroll
    for (int i = lane; i < DIM / 4; i += 32) {
        float4 v = p[i];
        s = fmaf(v.x, v.x, s); s = fmaf(v.y, v.y, s);
        s = fmaf(v.z, v.z, s); s = fmaf(v.w, v.w, s);
        __nv_bfloat162 h0, h1;
        h0.x = __float2bfloat16(v.x); h0.y = __float2bfloat16(v.y);
        h1.x = __float2bfloat16(v.z); h1.y = __float2bfloat16(v.w);
        dst[i * 2] = h0; dst[i * 2 + 1] = h1;
    }
    #pragma unroll
    for (int off = 16; off > 0; off >>= 1) s += __shfl_down_sync(0xFFFFFFFFu, s, off);
    if (lane == 0) g_zz[warp] = s;
}
__global__ void packnorm_w_kernel(const float* __restrict__ x) {
    int warp = (blockIdx.x * blockDim.x + threadIdx.x) >> 5;
    int lane = threadIdx.x & 31;
    if (warp >= N_CODE) return;
    const float4* p = (const float4*)(x + (size_t)warp * DIM);
    __nv_bfloat162* dst = (__nv_bfloat162*)(g_Bw + (size_t)warp * DIM);
    float s = 0.0f;
    #pragma unroll
    for (int i = lane; i < DIM / 4; i += 32) {
        float4 v = p[i];
        s = fmaf(v.x, v.x, s); s = fmaf(v.y, v.y, s);
        s = fmaf(v.z, v.z, s); s = fmaf(v.w, v.w, s);
        __nv_bfloat162 h0, h1;
        h0.x = __float2bfloat16(v.x); h0.y = __float2bfloat16(v.y);
        h1.x = __float2bfloat16(v.z); h1.y = __float2bfloat16(v.w);
        dst[i * 2] = h0; dst[i * 2 + 1] = h1;
    }
    #pragma unroll
    for (int off = 16; off > 0; off >>= 1) s += __shfl_down_sync(0xFFFFFFFFu, s, off);
    if (lane == 0) g_wn[warp] = s;
}

__global__ void init_kernel() {
    int i = blockIdx.x * blockDim.x + threadIdx.x;
    if (i < N_CODE) g_counts[i] = 0;
    if (i < B_ROWS) { g_rmin[i] = 0xFFFFFFFFu; g_ccnt[i] = 0; }
}

// ---------------- pass 1: hi-only bf16 HMMA screen + candidates ----------
// persistent grid = 2 CTAs/SM; unit tile 128x128, K=512. 256 threads = 8 warps:
// warpM = wid&1 (64 rows), warpN = wid>>1 in 0..3 (32 cols). Warp tile 64x32.
__global__ __launch_bounds__(256, 2) void vq_screen_kernel(int grid) {
    extern __shared__ char smem[];
    const uint32_t sb = smem_u32(smem);

    const int tid   = threadIdx.x;
    const int lane  = tid & 31;
    const int wid   = tid >> 5;
    const int warpM = wid & 1;
    const int warpN = wid >> 1;      // 0..3
    const int q     = lane & 3;
    const int bid   = blockIdx.x;

    const int nu = (UNITS - 1 - bid) / grid + 1;
    const int GT = nu * NKC;

    // pre-hoisted swizzled LDSM offsets: addr = base + (rel ^ (s<<5))
    uint32_t relA[4], relB[2];
    {
        const uint32_t hibA = (uint32_t)(lane >> 4);
        #pragma unroll
        for (int mi = 0; mi < 4; mi++) {
            uint32_t row = warpM * 64 + mi * 16 + (lane & 15);
            relA[mi] = row * 128u + ((hibA ^ (row & 7)) << 4);
        }
        const uint32_t hibB = (uint32_t)((lane >> 3) & 1);
        #pragma unroll
        for (int ni2 = 0; ni2 < 2; ni2++) {
            uint32_t row = warpN * 32 + ni2 * 16 + ((lane >> 4) << 3) + (lane & 7);
            relB[ni2] = row * 128u + ((hibB ^ (row & 7)) << 4);
        }
    }

    float acc[4][4][4];              // 4 mi x 4 n8 x 4 = 64 regs
    #pragma unroll
    for (int mi = 0; mi < 4; mi++)
        #pragma unroll
        for (int n8 = 0; n8 < 4; n8++)
            #pragma unroll
            for (int r = 0; r < 4; r++) acc[mi][n8][r] = 0.0f;

    auto load_tiles = [&](int g) {
        const int ui = g >> 3;
        const int kc = g & 7;
        const int w  = bid + ui * grid;
        const int mt = w >> 6;
        const int nt = w & 63;
        const uint32_t stage = sb + (uint32_t)(g % STAGES) * STAGE_BYTES;
        const __nv_bfloat16* Asrc = g_Az + (size_t)(mt * 128) * DIM + kc * 64;
        const __nv_bfloat16* Bsrc = g_Bw + (size_t)(nt * 128) * DIM + kc * 64;
        #pragma unroll
        for (int i = 0; i < 4; i++) {
            int lin = tid + 256 * i;           // 0..1023
            int row = lin >> 3, c = lin & 7;
            uint32_t off = (uint32_t)row * 128u + (uint32_t)((c ^ (row & 7)) << 4);
            cp16(stage + off, Asrc + (size_t)row * DIM + c * 8);
        }
        #pragma unroll
        for (int i = 0; i < 4; i++) {
            int lin = tid + 256 * i;           // 0..1023
            int row = lin >> 3, c = lin & 7;
            uint32_t off = (uint32_t)row * 128u + (uint32_t)((c ^ (row & 7)) << 4);
            cp16(stage + 16384u + off, Bsrc + (size_t)row * DIM + c * 8);
        }
        CP_COMMIT();
    };

    load_tiles(0);
    load_tiles(1);

    for (int g = 0; g < GT; g++) {
        if (g <= GT - 2) CP_WAIT1();
        else             CP_WAIT0();
        __syncthreads();
        if (g + 2 < GT) load_tiles(g + 2);

        const uint32_t Abase = sb + (uint32_t)(g % STAGES) * STAGE_BYTES;
        const uint32_t Bbase = Abase + 16384u;

        #pragma unroll
        for (int s = 0; s < 4; s++) {
            const uint32_t sx = (uint32_t)(s << 5);
            uint32_t afr[4][4];
            #pragma unroll
            for (int mi = 0; mi < 4; mi++)
                LDM_X4(afr[mi][0], afr[mi][1], afr[mi][2], afr[mi][3],
                       Abase + (relA[mi] ^ sx));
            uint32_t bfr[4][2];
            #pragma unroll
            for (int ni2 = 0; ni2 < 2; ni2++)
                LDM_X4(bfr[2 * ni2][0], bfr[2 * ni2][1],
                       bfr[2 * ni2 + 1][0], bfr[2 * ni2 + 1][1],
                       Bbase + (relB[ni2] ^ sx));
            #pragma unroll
            for (int mi = 0; mi < 4; mi++)
                #pragma unroll
                for (int n8 = 0; n8 < 4; n8++)
                    MMA_BF16(acc[mi][n8], afr[mi], bfr[n8]);
        }

        if ((g & 7) == 7) {
            // ---------- epilogue v3: early stale loads, single-pass distances ----
            const int ui = g >> 3;
            const int w  = bid + ui * grid;
            const int mt = w >> 6;
            const int nt = w & 63;
            const int cb = nt * 128 + warpN * 32 + 2 * q;
            const int rbase = mt * 128 + warpM * 64 + (lane >> 2);

            // stale running-min loads issued first; latency overlapped by pass A.
            // monotone-decreasing -> any stale value is a safe upper bound.
            float rmv[8];
            #pragma unroll
            for (int g8 = 0; g8 < 8; g8++)
                rmv[g8] = ord2f(__ldcg(&g_rmin[rbase + (g8 >> 1) * 16 + 8 * (g8 & 1)]));

            float wnv[8];
            #pragma unroll
            for (int n8 = 0; n8 < 4; n8++) {
                wnv[n8 * 2]     = __ldg(&g_wn[cb + n8 * 8]);
                wnv[n8 * 2 + 1] = __ldg(&g_wn[cb + n8 * 8 + 1]);
            }

            // pass A: distances overwrite acc; slice min; fire-and-forget RED
            float bvv[8];
            #pragma unroll
            for (int mi = 0; mi < 4; mi++) {
                #pragma unroll
                for (int h = 0; h < 2; h++) {
                    const int row = rbase + mi * 16 + 8 * h;
                    const float zzv = __ldg(&g_zz[row]);
                    float bv = __int_as_float(0x7f800000);
                    #pragma unroll
                    for (int n8 = 0; n8 < 4; n8++) {
                        #pragma unroll
                        for (int j = 0; j < 2; j++) {
                            float d = (zzv + wnv[n8 * 2 + j]) - 2.0f * acc[mi][n8][h * 2 + j];
                            acc[mi][n8][h * 2 + j] = d;
                            bv = fminf(bv, d);
                        }
                    }
                    #pragma unroll
                    for (int off = 1; off <= 2; off <<= 1)
                        bv = fminf(bv, __shfl_xor_sync(0xFFFFFFFFu, bv, off));
                    bvv[mi * 2 + h] = bv;
                    if (q == 0) atomicMin(&g_rmin[row], f2ord(bv));
                }
            }

            // pass B: threshold scan over stored distances
            #pragma unroll
            for (int mi = 0; mi < 4; mi++) {
                #pragma unroll
                for (int h = 0; h < 2; h++) {
                    const int g8 = mi * 2 + h;
                    const int row = rbase + mi * 16 + 8 * h;
                    const float thr = fminf(rmv[g8], bvv[g8]) + MARGIN;
                    #pragma unroll
                    for (int n8 = 0; n8 < 4; n8++) {
                        #pragma unroll
                        for (int j = 0; j < 2; j++) {
                            if (acc[mi][n8][h * 2 + j] < thr) {
                                int pos = atomicAdd(&g_ccnt[row], 1);
                                if (pos < CAP)
                                    g_cand[(size_t)row * CAP + pos] = cb + n8 * 8 + j;
                            }
                        }
                    }
                }
            }
            #pragma unroll
            for (int mi = 0; mi < 4; mi++)
                #pragma unroll
                for (int n8 = 0; n8 < 4; n8++)
                    #pragma unroll
                    for (int r = 0; r < 4; r++) acc[mi][n8][r] = 0.0f;
        }
    }
}

// ------ pass 2: exact fp32 rescore + gather + SSE + histogram (fused) ------
// one warp per row; lexicographic (d, code) min = first-occurrence argmin.
__global__ __launch_bounds__(256, 4) void rescore_gather_kernel(
        const float* __restrict__ z, const float* __restrict__ W,
        float* __restrict__ out) {
    const int lane = threadIdx.x & 31;
    const int row = blockIdx.x * 8 + (threadIdx.x >> 5);

    float zr[16];
    const float4* zp = (const float4*)(z + (size_t)row * DIM + lane * 16);
    #pragma unroll
    for (int i = 0; i < 4; i++) {
        float4 v = zp[i];
        zr[i * 4] = v.x; zr[i * 4 + 1] = v.y; zr[i * 4 + 2] = v.z; zr[i * 4 + 3] = v.w;
    }
    const float zzv = g_zz[row];
    const int cnt = g_ccnt[row];

    float bv = __int_as_float(0x7f800000);
    int bc = 0x7FFFFFFF;

    const int n = (cnt <= CAP) ? cnt : N_CODE;   // overflow fallback: full scan
    for (int i = 0; i < n; i++) {
        const int code = (cnt <= CAP) ? g_cand[(size_t)row * CAP + i] : i;
        const float4* wp = (const float4*)(W + (size_t)code * DIM + lane * 16);
        float s = 0.0f;
        #pragma unroll
        for (int k = 0; k < 4; k++) {
            float4 v = wp[k];
            s = fmaf(zr[k * 4], v.x, s);
            s = fmaf(zr[k * 4 + 1], v.y, s);
            s = fmaf(zr[k * 4 + 2], v.z, s);
            s = fmaf(zr[k * 4 + 3], v.w, s);
        }
        #pragma unroll
        for (int off = 16; off > 0; off >>= 1) s += __shfl_xor_sync(0xFFFFFFFFu, s, off);
        const float d = (zzv + g_wn[code]) - 2.0f * s;
        if (d < bv || (d == bv && code < bc)) { bv = d; bc = code; }
    }

    // gather winner row (L2-hot), write quantized output, per-row SSE
    const float4* wp = (const float4*)(W + (size_t)bc * DIM + lane * 16);
    float4* op = (float4*)out + (size_t)row * (DIM / 4) + lane * 4;
    float sse = 0.0f;
    #pragma unroll
    for (int k = 0; k < 4; k++) {
        float4 v = wp[k];
        op[k] = v;
        float d0 = zr[k * 4]     - v.x;
        float d1 = zr[k * 4 + 1] - v.y;
        float d2 = zr[k * 4 + 2] - v.z;
        float d3 = zr[k * 4 + 3] - v.w;
        sse += d0 * d0 + d1 * d1 + d2 * d2 + d3 * d3;
    }
    #pragma unroll
    for (int off = 16; off > 0; off >>= 1) sse += __shfl_xor_sync(0xFFFFFFFFu, sse, off);

    if (lane == 0) {
        g_rowsse[row] = sse;
        out[BD + 1 + row] = (float)bc;
        atomicAdd(&g_counts[bc], 1);
    }
}

// ---------------- final loss ----------------
__global__ void finalize_kernel(float* __restrict__ out) {
    __shared__ float sh[1024];
    int t = threadIdx.x;
    float s = 0.0f;
    for (int i = t; i < B_ROWS; i += 1024) s += g_rowsse[i];
    sh[t] = s;
    __syncthreads();
    #pragma unroll
    for (int off = 512; off > 0; off >>= 1) {
        if (t < off) sh[t] += sh[t + off];
        __syncthreads();
    }
    float sse = sh[0];
    __syncthreads();
    float e = 0.0f;
    for (int i = t; i < N_CODE; i += 1024) {
        float c = (float)g_counts[i];
        float p = c * (1.0f / (float)B_ROWS);
        e -= p * logf(p + 1e-10f);
    }
    sh[t] = e;
    __syncthreads();
    #pragma unroll
    for (int off = 512; off > 0; off >>= 1) {
        if (t < off) sh[t] += sh[t + off];
        __syncthreads();
    }
    if (t == 0) {
        float mse = sse / (float)BD;
        float entropy_loss = 1.0f - sh[0] / logf((float)N_CODE);
        out[BD] = 1.25f * mse + 0.1f * entropy_loss;
    }
}

// ---------------- launch ----------------
extern "C" void kernel_launch(void* const* d_in, const int* in_sizes, int n_in,
                              void* d_out, int out_size) {
    const float* z = (const float*)d_in[0];
    const float* W = (const float*)d_in[1];
    float* out = (float*)d_out;

    int nsm = 148;
    cudaDeviceGetAttribute(&nsm, cudaDevAttrMultiProcessorCount, 0);
    const int grid = 2 * nsm;

    cudaFuncSetAttribute(vq_screen_kernel,
                         cudaFuncAttributeMaxDynamicSharedMemorySize, SMEM_TOTAL);

    packnorm_z_kernel<<<B_ROWS / 8, 256>>>(z);
    packnorm_w_kernel<<<N_CODE / 8, 256>>>(W);
    init_kernel<<<B_ROWS / 256, 256>>>();

    vq_screen_kernel<<<grid, 256, SMEM_TOTAL>>>(grid);

    rescore_gather_kernel<<<B_ROWS / 8, 256>>>(z, W, out);
    finalize_kernel<<<1, 1024>>>(out);
}

// round 14
// speedup vs baseline: 4.2826x; 4.2826x over previous
#include <cuda_runtime.h>
#include <cuda_bf16.h>
#include <cstdint>
#include <math.h>

#define B_ROWS 32768
#define N_CODE 8192
#define DIM    512
#define BD     (B_ROWS * DIM)

#define UNITS  16384           // 256 mt x 64 nt, unit tile 128x128
#define NKC    8               // K-chunks of 64 (K=512, hi-only)
#define STAGES 3
#define STAGE_BYTES 32768      // A 16K (128x128B) + B 16K (128x128B)
#define SMEM_TOTAL (STAGES * STAGE_BYTES)   // 96 KB -> 2 CTAs/SM

#define CAP    512
#define MARGIN 0.75f

// ---------------- device scratch ----------------
__device__ __nv_bfloat16 g_Az[(size_t)B_ROWS * DIM];   // 32 MB (hi only)
__device__ __nv_bfloat16 g_Bw[(size_t)N_CODE * DIM];   // 8 MB
__device__ float g_zz[B_ROWS];
__device__ float g_wn[N_CODE];
__device__ unsigned g_rmin[B_ROWS];        // ordered-float running min
__device__ int g_ccnt[B_ROWS];
__device__ int g_cand[(size_t)B_ROWS * CAP];   // 64 MB
__device__ int g_counts[N_CODE];
__device__ float g_rowsse[B_ROWS];

// ---------------- helpers ----------------
__device__ __forceinline__ uint32_t smem_u32(const void* p) {
    uint32_t a;
    asm("{ .reg .u64 t; cvta.to.shared.u64 t, %1; cvt.u32.u64 %0, t; }" : "=r"(a) : "l"(p));
    return a;
}
__device__ __forceinline__ void cp16(uint32_t dst, const void* src) {
    asm volatile("cp.async.cg.shared.global [%0], [%1], 16;" :: "r"(dst), "l"(src));
}
#define CP_COMMIT() asm volatile("cp.async.commit_group;" ::: "memory")
#define CP_WAIT0()  asm volatile("cp.async.wait_group 0;" ::: "memory")
#define CP_WAIT1()  asm volatile("cp.async.wait_group 1;" ::: "memory")

#define LDM_X4(r0, r1, r2, r3, a)                                              \
    asm volatile("ldmatrix.sync.aligned.m8n8.x4.shared.b16 {%0,%1,%2,%3}, [%4];" \
        : "=r"(r0), "=r"(r1), "=r"(r2), "=r"(r3) : "r"(a))

#define MMA_BF16(d, a, b)                                                      \
    asm volatile("mma.sync.aligned.m16n8k16.row.col.f32.bf16.bf16.f32 "        \
        "{%0,%1,%2,%3},{%4,%5,%6,%7},{%8,%9},{%0,%1,%2,%3};"                   \
        : "+f"((d)[0]), "+f"((d)[1]), "+f"((d)[2]), "+f"((d)[3])               \
        : "r"((a)[0]), "r"((a)[1]), "r"((a)[2]), "r"((a)[3]),                  \
          "r"((b)[0]), "r"((b)[1]))

__device__ __forceinline__ uint32_t f2ord(float f) {
    uint32_t u = __float_as_uint(f);
    return (u & 0x80000000u) ? ~u : (u | 0x80000000u);
}
__device__ __forceinline__ float ord2f(uint32_t k) {
    return (k & 0x80000000u) ? __uint_as_float(k ^ 0x80000000u)
                             : __uint_as_float(~k);
}

// ---------------- fused pack (fp32 -> bf16 hi) + row norm ----------------
__global__ void packnorm_z_kernel(const float* __restrict__ x) {
    int warp = (blockIdx.x * blockDim.x + threadIdx.x) >> 5;
    int lane = threadIdx.x & 31;
    if (warp >= B_ROWS) return;
    const float4* p = (const float4*)(x + (size_t)warp * DIM);
    __nv_bfloat162* dst = (__nv_bfloat162*)(g_Az + (size_t)warp * DIM);
    float s = 0.0f;
    #pragma unroll
    for (int i = lane; i < DIM / 4; i += 32) {
        float4 v = p[i];
        s = fmaf(v.x, v.x, s); s = fmaf(v.y, v.y, s);
        s = fmaf(v.z, v.z, s); s = fmaf(v.w, v.w, s);
        __nv_bfloat162 h0, h1;
        h0.x = __float2bfloat16(v.x); h0.y = __float2bfloat16(v.y);
        h1.x = __float2bfloat16(v.z); h1.y = __float2bfloat16(v.w);
        dst[i * 2] = h0; dst[i * 2 + 1] = h1;
    }
    #pragma unroll
    for (int off = 16; off > 0; off >>= 1) s += __shfl_down_sync(0xFFFFFFFFu, s, off);
    if (lane == 0) g_zz[warp] = s;
}
__global__ void packnorm_w_kernel(const float* __restrict__ x) {
    int warp = (blockIdx.x * blockDim.x + threadIdx.x) >> 5;
    int lane = threadIdx.x & 31;
    if (warp >= N_CODE) return;
    const float4* p = (const float4*)(x + (size_t)warp * DIM);
    __nv_bfloat162* dst = (__nv_bfloat162*)(g_Bw + (size_t)warp * DIM);
    float s = 0.0f;
    #pragma unroll
    for (int i = lane; i < DIM / 4; i += 32) {
        float4 v = p[i];
        s = fmaf(v.x, v.x, s); s = fmaf(v.y, v.y, s);
        s = fmaf(v.z, v.z, s); s = fmaf(v.w, v.w, s);
        __nv_bfloat162 h0, h1;
        h0.x = __float2bfloat16(v.x); h0.y = __float2bfloat16(v.y);
        h1.x = __float2bfloat16(v.z); h1.y = __float2bfloat16(v.w);
        dst[i * 2] = h0; dst[i * 2 + 1] = h1;
    }
    #pragma unroll
    for (int off = 16; off > 0; off >>= 1) s += __shfl_down_sync(0xFFFFFFFFu, s, off);
    if (lane == 0) g_wn[warp] = s;
}

__global__ void init_kernel() {
    int i = blockIdx.x * blockDim.x + threadIdx.x;
    if (i < N_CODE) g_counts[i] = 0;
    if (i < B_ROWS) { g_rmin[i] = 0xFFFFFFFFu; g_ccnt[i] = 0; }
}

// ---------------- pass 1: hi-only bf16 HMMA screen + candidates ----------
// persistent grid = 2 CTAs/SM; unit tile 128x128, K=512. 256 threads = 8 warps:
// warpM = wid&1 (64 rows), warpN = wid>>1 in 0..3 (32 cols). Warp tile 64x32.
__global__ __launch_bounds__(256, 2) void vq_screen_kernel(int grid) {
    extern __shared__ char smem[];
    const uint32_t sb = smem_u32(smem);

    const int tid   = threadIdx.x;
    const int lane  = tid & 31;
    const int wid   = tid >> 5;
    const int warpM = wid & 1;
    const int warpN = wid >> 1;      // 0..3
    const int q     = lane & 3;
    const int bid   = blockIdx.x;

    const int nu = (UNITS - 1 - bid) / grid + 1;
    const int GT = nu * NKC;

    // pre-hoisted swizzled LDSM offsets: addr = base + (rel ^ (s<<5))
    uint32_t relA[4], relB[2];
    {
        const uint32_t hibA = (uint32_t)(lane >> 4);
        #pragma unroll
        for (int mi = 0; mi < 4; mi++) {
            uint32_t row = warpM * 64 + mi * 16 + (lane & 15);
            relA[mi] = row * 128u + ((hibA ^ (row & 7)) << 4);
        }
        const uint32_t hibB = (uint32_t)((lane >> 3) & 1);
        #pragma unroll
        for (int ni2 = 0; ni2 < 2; ni2++) {
            uint32_t row = warpN * 32 + ni2 * 16 + ((lane >> 4) << 3) + (lane & 7);
            relB[ni2] = row * 128u + ((hibB ^ (row & 7)) << 4);
        }
    }

    float acc[4][4][4];              // 4 mi x 4 n8 x 4 = 64 regs
    #pragma unroll
    for (int mi = 0; mi < 4; mi++)
        #pragma unroll
        for (int n8 = 0; n8 < 4; n8++)
            #pragma unroll
            for (int r = 0; r < 4; r++) acc[mi][n8][r] = 0.0f;

    auto load_tiles = [&](int g) {
        const int ui = g >> 3;
        const int kc = g & 7;
        const int w  = bid + ui * grid;
        const int mt = w >> 6;
        const int nt = w & 63;
        const uint32_t stage = sb + (uint32_t)(g % STAGES) * STAGE_BYTES;
        const __nv_bfloat16* Asrc = g_Az + (size_t)(mt * 128) * DIM + kc * 64;
        const __nv_bfloat16* Bsrc = g_Bw + (size_t)(nt * 128) * DIM + kc * 64;
        #pragma unroll
        for (int i = 0; i < 4; i++) {
            int lin = tid + 256 * i;           // 0..1023
            int row = lin >> 3, c = lin & 7;
            uint32_t off = (uint32_t)row * 128u + (uint32_t)((c ^ (row & 7)) << 4);
            cp16(stage + off, Asrc + (size_t)row * DIM + c * 8);
        }
        #pragma unroll
        for (int i = 0; i < 4; i++) {
            int lin = tid + 256 * i;           // 0..1023
            int row = lin >> 3, c = lin & 7;
            uint32_t off = (uint32_t)row * 128u + (uint32_t)((c ^ (row & 7)) << 4);
            cp16(stage + 16384u + off, Bsrc + (size_t)row * DIM + c * 8);
        }
        CP_COMMIT();
    };

    load_tiles(0);
    load_tiles(1);

    for (int g = 0; g < GT; g++) {
        if (g <= GT - 2) CP_WAIT1();
        else             CP_WAIT0();
        __syncthreads();
        if (g + 2 < GT) load_tiles(g + 2);

        const uint32_t Abase = sb + (uint32_t)(g % STAGES) * STAGE_BYTES;
        const uint32_t Bbase = Abase + 16384u;

        #pragma unroll
        for (int s = 0; s < 4; s++) {
            const uint32_t sx = (uint32_t)(s << 5);
            uint32_t afr[4][4];
            #pragma unroll
            for (int mi = 0; mi < 4; mi++)
                LDM_X4(afr[mi][0], afr[mi][1], afr[mi][2], afr[mi][3],
                       Abase + (relA[mi] ^ sx));
            uint32_t bfr[4][2];
            #pragma unroll
            for (int ni2 = 0; ni2 < 2; ni2++)
                LDM_X4(bfr[2 * ni2][0], bfr[2 * ni2][1],
                       bfr[2 * ni2 + 1][0], bfr[2 * ni2 + 1][1],
                       Bbase + (relB[ni2] ^ sx));
            #pragma unroll
            for (int mi = 0; mi < 4; mi++)
                #pragma unroll
                for (int n8 = 0; n8 < 4; n8++)
                    MMA_BF16(acc[mi][n8], afr[mi], bfr[n8]);
        }

        if ((g & 7) == 7) {
            // ---- epilogue (R11 order): pass A -> fresh loads -> scan ----
            const int ui = g >> 3;
            const int w  = bid + ui * grid;
            const int mt = w >> 6;
            const int nt = w & 63;
            const int cb = nt * 128 + warpN * 32 + 2 * q;
            const int rbase = mt * 128 + warpM * 64 + (lane >> 2);

            float wnv[8];
            #pragma unroll
            for (int n8 = 0; n8 < 4; n8++) {
                wnv[n8 * 2]     = __ldg(&g_wn[cb + n8 * 8]);
                wnv[n8 * 2 + 1] = __ldg(&g_wn[cb + n8 * 8 + 1]);
            }

            // pass A: distances overwrite acc; slice min; fire-and-forget RED
            float bvv[8];
            #pragma unroll
            for (int mi = 0; mi < 4; mi++) {
                #pragma unroll
                for (int h = 0; h < 2; h++) {
                    const int row = rbase + mi * 16 + 8 * h;
                    const float zzv = __ldg(&g_zz[row]);
                    float bv = __int_as_float(0x7f800000);
                    #pragma unroll
                    for (int n8 = 0; n8 < 4; n8++) {
                        #pragma unroll
                        for (int j = 0; j < 2; j++) {
                            float d = (zzv + wnv[n8 * 2 + j]) - 2.0f * acc[mi][n8][h * 2 + j];
                            acc[mi][n8][h * 2 + j] = d;
                            bv = fminf(bv, d);
                        }
                    }
                    #pragma unroll
                    for (int off = 1; off <= 2; off <<= 1)
                        bv = fminf(bv, __shfl_xor_sync(0xFFFFFFFFu, bv, off));
                    bvv[mi * 2 + h] = bv;
                    if (q == 0) atomicMin(&g_rmin[row], f2ord(bv));
                }
            }

            // loads AFTER atomics: fresher thresholds -> bounded candidate counts
            float rmv[8];
            #pragma unroll
            for (int g8 = 0; g8 < 8; g8++)
                rmv[g8] = ord2f(__ldcg(&g_rmin[rbase + (g8 >> 1) * 16 + 8 * (g8 & 1)]));

            // pass B: threshold scan over stored distances (staleness-safe)
            #pragma unroll
            for (int mi = 0; mi < 4; mi++) {
                #pragma unroll
                for (int h = 0; h < 2; h++) {
                    const int g8 = mi * 2 + h;
                    const int row = rbase + mi * 16 + 8 * h;
                    const float thr = fminf(rmv[g8], bvv[g8]) + MARGIN;
                    #pragma unroll
                    for (int n8 = 0; n8 < 4; n8++) {
                        #pragma unroll
                        for (int j = 0; j < 2; j++) {
                            if (acc[mi][n8][h * 2 + j] < thr) {
                                int pos = atomicAdd(&g_ccnt[row], 1);
                                if (pos < CAP)
                                    g_cand[(size_t)row * CAP + pos] = cb + n8 * 8 + j;
                            }
                        }
                    }
                }
            }
            #pragma unroll
            for (int mi = 0; mi < 4; mi++)
                #pragma unroll
                for (int n8 = 0; n8 < 4; n8++)
                    #pragma unroll
                    for (int r = 0; r < 4; r++) acc[mi][n8][r] = 0.0f;
        }
    }
}

// ------ pass 2: exact fp32 rescore + gather + SSE + histogram (fused) ------
// one warp per row; lexicographic (d, code) min = first-occurrence argmin.
__global__ __launch_bounds__(256, 4) void rescore_gather_kernel(
        const float* __restrict__ z, const float* __restrict__ W,
        float* __restrict__ out) {
    const int lane = threadIdx.x & 31;
    const int row = blockIdx.x * 8 + (threadIdx.x >> 5);

    float zr[16];
    const float4* zp = (const float4*)(z + (size_t)row * DIM + lane * 16);
    #pragma unroll
    for (int i = 0; i < 4; i++) {
        float4 v = zp[i];
        zr[i * 4] = v.x; zr[i * 4 + 1] = v.y; zr[i * 4 + 2] = v.z; zr[i * 4 + 3] = v.w;
    }
    const float zzv = g_zz[row];
    const int cnt = g_ccnt[row];

    float bv = __int_as_float(0x7f800000);
    int bc = 0x7FFFFFFF;

    const int n = (cnt <= CAP) ? cnt : N_CODE;   // overflow fallback: full scan
    for (int i = 0; i < n; i++) {
        const int code = (cnt <= CAP) ? g_cand[(size_t)row * CAP + i] : i;
        const float4* wp = (const float4*)(W + (size_t)code * DIM + lane * 16);
        float s = 0.0f;
        #pragma unroll
        for (int k = 0; k < 4; k++) {
            float4 v = wp[k];
            s = fmaf(zr[k * 4], v.x, s);
            s = fmaf(zr[k * 4 + 1], v.y, s);
            s = fmaf(zr[k * 4 + 2], v.z, s);
            s = fmaf(zr[k * 4 + 3], v.w, s);
        }
        #pragma unroll
        for (int off = 16; off > 0; off >>= 1) s += __shfl_xor_sync(0xFFFFFFFFu, s, off);
        const float d = (zzv + g_wn[code]) - 2.0f * s;
        if (d < bv || (d == bv && code < bc)) { bv = d; bc = code; }
    }

    // gather winner row (L2-hot), write quantized output, per-row SSE
    const float4* wp = (const float4*)(W + (size_t)bc * DIM + lane * 16);
    float4* op = (float4*)out + (size_t)row * (DIM / 4) + lane * 4;
    float sse = 0.0f;
    #pragma unroll
    for (int k = 0; k < 4; k++) {
        float4 v = wp[k];
        op[k] = v;
        float d0 = zr[k * 4]     - v.x;
        float d1 = zr[k * 4 + 1] - v.y;
        float d2 = zr[k * 4 + 2] - v.z;
        float d3 = zr[k * 4 + 3] - v.w;
        sse += d0 * d0 + d1 * d1 + d2 * d2 + d3 * d3;
    }
    #pragma unroll
    for (int off = 16; off > 0; off >>= 1) sse += __shfl_xor_sync(0xFFFFFFFFu, sse, off);

    if (lane == 0) {
        g_rowsse[row] = sse;
        out[BD + 1 + row] = (float)bc;
        atomicAdd(&g_counts[bc], 1);
    }
}

// ---------------- final loss ----------------
__global__ void finalize_kernel(float* __restrict__ out) {
    __shared__ float sh[1024];
    int t = threadIdx.x;
    float s = 0.0f;
    for (int i = t; i < B_ROWS; i += 1024) s += g_rowsse[i];
    sh[t] = s;
    __syncthreads();
    #pragma unroll
    for (int off = 512; off > 0; off >>= 1) {
        if (t < off) sh[t] += sh[t + off];
        __syncthreads();
    }
    float sse = sh[0];
    __syncthreads();
    float e = 0.0f;
    for (int i = t; i < N_CODE; i += 1024) {
        float c = (float)g_counts[i];
        float p = c * (1.0f / (float)B_ROWS);
        e -= p * logf(p + 1e-10f);
    }
    sh[t] = e;
    __syncthreads();
    #pragma unroll
    for (int off = 512; off > 0; off >>= 1) {
        if (t < off) sh[t] += sh[t + off];
        __syncthreads();
    }
    if (t == 0) {
        float mse = sse / (float)BD;
        float entropy_loss = 1.0f - sh[0] / logf((float)N_CODE);
        out[BD] = 1.25f * mse + 0.1f * entropy_loss;
    }
}

// ---------------- launch ----------------
extern "C" void kernel_launch(void* const* d_in, const int* in_sizes, int n_in,
                              void* d_out, int out_size) {
    const float* z = (const float*)d_in[0];
    const float* W = (const float*)d_in[1];
    float* out = (float*)d_out;

    int nsm = 148;
    cudaDeviceGetAttribute(&nsm, cudaDevAttrMultiProcessorCount, 0);
    const int grid = 2 * nsm;

    cudaFuncSetAttribute(vq_screen_kernel,
                         cudaFuncAttributeMaxDynamicSharedMemorySize, SMEM_TOTAL);

    packnorm_z_kernel<<<B_ROWS / 8, 256>>>(z);
    packnorm_w_kernel<<<N_CODE / 8, 256>>>(W);
    init_kernel<<<B_ROWS / 256, 256>>>();

    vq_screen_kernel<<<grid, 256, SMEM_TOTAL>>>(grid);

    rescore_gather_kernel<<<B_ROWS / 8, 256>>>(z, W, out);
    finalize_kernel<<<1, 1024>>>(out);
}